// round 14
// baseline (speedup 1.0000x reference)
#include <cuda_runtime.h>
#include <math.h>
#include <stdint.h>

#define B_  64
#define S_  512
#define I_  300
#define H_  512
#define T_  25
#define G4_ 2048

// d_out layout (float32): [loss(1)] [logits B*S*T] [tags B*S] [pred_mask B*S]
#define LOGITS_OFF 1
#define TAGS_OFF   (1 + B_*S_*T_)
#define PM_OFF     (TAGS_OFF + B_*S_)

typedef unsigned long long u64;

// ---------------- device scratch (static, no allocations) -------------------
__device__ float g_pre[(size_t)2 * S_ * B_ * G4_];   // [dir][t][b][g]
__device__ float g_hf[(size_t)B_ * S_ * H_];         // forward outputs
__device__ float g_hb[(size_t)B_ * S_ * H_];         // backward outputs (un-reversed)
__device__ float g_hbuf[2][2][B_ * H_];              // [buf][dir][b*H+u]
__device__ int   g_len[B_];
__device__ float g_llh[B_];

// two-level per-direction barrier state (monotonic, replay-safe)
__device__ __align__(128) u64 g_grp[8][16];          // [dir*4+grp][0]
__device__ __align__(128) u64 g_mst[2][16];          // [dir][0]
__device__ __align__(128) u64 g_rel[2][16];          // [dir][0]

// ---------------- packed f32x2 FMA ------------------------------------------
__device__ __forceinline__ void ffma2(u64 &d, u64 a, u64 b) {
    asm("fma.rn.f32x2 %0, %1, %2, %0;" : "+l"(d) : "l"(a), "l"(b));
}
__device__ __forceinline__ float f2sum(u64 v) {
    float lo = __uint_as_float((unsigned)(v & 0xffffffffu));
    float hi = __uint_as_float((unsigned)(v >> 32));
    return lo + hi;
}

// ---------------- two-level barrier: 64 blocks of one direction -------------
__device__ __forceinline__ void lstm_barrier(int dir, int grp) {
    __syncthreads();
    if (threadIdx.x == 0) {
        __threadfence();
        u64 tk = atomicAdd(&g_grp[dir * 4 + grp][0], 1ull);
        u64 round = tk >> 4;
        if ((tk & 15ull) == 15ull) {
            u64 t2 = atomicAdd(&g_mst[dir][0], 1ull);
            if ((t2 & 3ull) == 3ull) {
                u64 rel = (t2 >> 2) + 1ull;
                asm volatile("st.release.gpu.global.u64 [%0], %1;"
                             :: "l"(&g_rel[dir][0]), "l"(rel) : "memory");
            }
        }
        u64 target = round + 1ull;
        u64 v;
        do {
            asm volatile("ld.acquire.gpu.global.u64 %0, [%1];"
                         : "=l"(v) : "l"(&g_rel[dir][0]) : "memory");
        } while (v < target);
    }
    __syncthreads();
}

__device__ __forceinline__ float sigf(float x) { return 1.0f / (1.0f + expf(-x)); }

// ---------------- K0: lengths + pred_mask -----------------------------------
__global__ void k_len(const int* __restrict__ mask, float* __restrict__ out) {
    __shared__ int sred[256];
    int b = blockIdx.x;
    int s = 0;
    for (int t = threadIdx.x; t < S_; t += 256) s += mask[b * S_ + t];
    sred[threadIdx.x] = s;
    __syncthreads();
    for (int o = 128; o > 0; o >>= 1) {
        if (threadIdx.x < o) sred[threadIdx.x] += sred[threadIdx.x + o];
        __syncthreads();
    }
    int L = sred[0];
    if (threadIdx.x == 0) g_len[b] = L;
    for (int t = threadIdx.x; t < S_; t += 256)
        out[PM_OFF + b * S_ + t] = (t < L) ? 1.0f : 0.0f;
}

// ---------------- K1: pre-activations x@W_ih^T + b --------------------------
#define KC1 20
__global__ __launch_bounds__(256) void k_pre(const float* __restrict__ x,
                                             const float* __restrict__ Wf,
                                             const float* __restrict__ bf,
                                             const float* __restrict__ Wb,
                                             const float* __restrict__ bb) {
    __shared__ float As[64 * KC1];   // [b][k]
    __shared__ float Bs[64 * KC1];   // [g][k]
    const int gc  = blockIdx.x;
    const int t   = blockIdx.y;
    const int dir = blockIdx.z;
    const float* W    = dir ? Wb : Wf;
    const float* bias = dir ? bb : bf;
    const int g0  = gc * 64;
    const int tid = threadIdx.x;
    const int gg  = tid & 15;
    const int bb_ = tid >> 4;

    int ib[5], ik[5];
    const float* srcA[5];
    const float* srcB[5];
#pragma unroll
    for (int it = 0; it < 5; ++it) {
        int e = tid + 256 * it;
        ib[it] = e / KC1;
        ik[it] = e - ib[it] * KC1;
        int b = ib[it];
        int L = g_len[b];
        int tt = t;
        if (dir && t < L) tt = L - 1 - t;
        srcA[it] = &x[((size_t)b * S_ + tt) * I_ + ik[it]];
        srcB[it] = &W[(size_t)(g0 + b) * I_ + ik[it]];
    }

    float rA[5], rB[5];
#pragma unroll
    for (int it = 0; it < 5; ++it) { rA[it] = srcA[it][0]; rB[it] = srcB[it][0]; }

    u64 acc[4][4];
#pragma unroll
    for (int i = 0; i < 4; ++i)
#pragma unroll
        for (int j = 0; j < 4; ++j) acc[i][j] = 0ull;

    for (int c = 0; c < 15; ++c) {
#pragma unroll
        for (int it = 0; it < 5; ++it) {
            As[ib[it] * KC1 + ik[it]] = rA[it];
            Bs[ib[it] * KC1 + ik[it]] = rB[it];
        }
        __syncthreads();
        if (c < 14) {
            const int k0 = (c + 1) * KC1;
#pragma unroll
            for (int it = 0; it < 5; ++it) { rA[it] = srcA[it][k0]; rB[it] = srcB[it][k0]; }
        }
#pragma unroll
        for (int kq = 0; kq < KC1 / 4; ++kq) {
            ulonglong2 av[4], bv[4];
#pragma unroll
            for (int jj = 0; jj < 4; ++jj)
                av[jj] = *reinterpret_cast<const ulonglong2*>(&As[(bb_ + 16 * jj) * KC1 + kq * 4]);
#pragma unroll
            for (int i = 0; i < 4; ++i)
                bv[i] = *reinterpret_cast<const ulonglong2*>(&Bs[(gg + 16 * i) * KC1 + kq * 4]);
#pragma unroll
            for (int i = 0; i < 4; ++i)
#pragma unroll
                for (int jj = 0; jj < 4; ++jj) {
                    ffma2(acc[i][jj], av[jj].x, bv[i].x);
                    ffma2(acc[i][jj], av[jj].y, bv[i].y);
                }
        }
        __syncthreads();
    }
#pragma unroll
    for (int i = 0; i < 4; ++i) {
        int g = g0 + gg + 16 * i;
        float bv = bias[g];
#pragma unroll
        for (int jj = 0; jj < 4; ++jj) {
            int b = bb_ + 16 * jj;
            g_pre[(((size_t)dir * S_ + t) * B_ + b) * G4_ + g] = f2sum(acc[i][jj]) + bv;
        }
    }
}

// ---------------- K2: persistent bidirectional LSTM scan --------------------
// 128 blocks x 512 threads (4 warps/SMSP). Block j: dir=j>>6, u0=(j&63)*8.
// Thread: kq4 = tid>>7 (K quarter, 128 k each); r = tid&127: rg=r&7, bgrp=r>>3.
// Micro-tile 4 gates x 4 batches (unchanged from round 11).
// h tile staged via TMA in TWO halves (two mbarriers) overlapping compute.
#define WS_STR 516
#define HA_STR 516
#define RED_STR 17
__global__ __launch_bounds__(512, 1) void k_lstm(const float* __restrict__ Whf,
                                                 const float* __restrict__ Whb) {
    extern __shared__ float sm[];
    float* Ws   = sm;                               // 32*516
    float* hall = sm + 32 * WS_STR;                 // 64*516
    float* red  = sm + 32 * WS_STR + 64 * HA_STR;   // 384*17
    __shared__ __align__(8) u64 mbarA, mbarB;

    const int j    = blockIdx.x;
    const int dir  = j >> 6;
    const int grp  = (j & 63) >> 4;     // barrier group 0..3
    const int u0   = (j & 63) * 8;
    const int tid  = threadIdx.x;
    const int kq4  = tid >> 7;          // K quarter 0..3
    const int r    = tid & 127;
    const int rg   = r & 7;             // hidden-unit within slice
    const int bgrp = r >> 3;            // 0..15 ; b = bgrp + 16*jj
    const int u    = u0 + rg;
    const int kbeg = kq4 << 7;          // 0,128,256,384

    const float* Wh = dir ? Whb : Whf;
    const unsigned hall_s = (unsigned)__cvta_generic_to_shared(hall);
    const unsigned mbA    = (unsigned)__cvta_generic_to_shared(&mbarA);
    const unsigned mbB    = (unsigned)__cvta_generic_to_shared(&mbarB);

    if (tid == 0) {
        asm volatile("mbarrier.init.shared.b64 [%0], 1;" :: "r"(mbA) : "memory");
        asm volatile("mbarrier.init.shared.b64 [%0], 1;" :: "r"(mbB) : "memory");
    }

    // load persistent W slice: row rr -> W_hh[(rr>>3)*512 + u0 + (rr&7)][k]
    for (int e = tid; e < 32 * 512; e += 512) {
        int rr = e >> 9, k = e & 511;
        int grow = (rr >> 3) * H_ + u0 + (rr & 7);
        Ws[rr * WS_STR + k] = Wh[(size_t)grow * H_ + k];
    }
    // zero read-buffer (buf 1) for our slice
    for (int e = tid; e < 64 * 8; e += 512) {
        int b = e >> 3, uu = e & 7;
        g_hbuf[1][dir][b * H_ + u0 + uu] = 0.0f;
    }

    float creg[4] = {0.f, 0.f, 0.f, 0.f};
    float hreg[4] = {0.f, 0.f, 0.f, 0.f};
    int Lb[4];
#pragma unroll
    for (int jj = 0; jj < 4; ++jj) Lb[jj] = g_len[bgrp + 16 * jj];

    lstm_barrier(dir, grp);

    for (int t = 0; t < S_; ++t) {
        const float* hsrc = g_hbuf[(t & 1) ^ 1][dir];

        // prefetch pre-activation gates (only the epilogue quarter needs them)
        float pf[4][4];
        if (kq4 == 0) {
            const float* pbase = &g_pre[(((size_t)dir * S_ + t) * B_) * G4_];
#pragma unroll
            for (int jj = 0; jj < 4; ++jj) {
                const float* p = pbase + (size_t)(bgrp + 16 * jj) * G4_ + u;
                pf[0][jj] = p[0];
                pf[1][jj] = p[512];
                pf[2][jj] = p[1024];
                pf[3][jj] = p[1536];
            }
        }

        // stage h tile via TMA in two K-halves (1KB per row per half)
        if (tid == 0) {
            asm volatile("mbarrier.arrive.expect_tx.shared.b64 _, [%0], %1;"
                         :: "r"(mbA), "r"(64u * 1024u) : "memory");
#pragma unroll 4
            for (int b = 0; b < 64; ++b) {
                unsigned dst = hall_s + (unsigned)(b * HA_STR * 4);
                const float* src = hsrc + b * 512;
                asm volatile(
                    "cp.async.bulk.shared::cta.global.mbarrier::complete_tx::bytes [%0], [%1], %2, [%3];"
                    :: "r"(dst), "l"(src), "r"(1024u), "r"(mbA) : "memory");
            }
            asm volatile("mbarrier.arrive.expect_tx.shared.b64 _, [%0], %1;"
                         :: "r"(mbB), "r"(64u * 1024u) : "memory");
#pragma unroll 4
            for (int b = 0; b < 64; ++b) {
                unsigned dst = hall_s + (unsigned)((b * HA_STR + 256) * 4);
                const float* src = hsrc + b * 512 + 256;
                asm volatile(
                    "cp.async.bulk.shared::cta.global.mbarrier::complete_tx::bytes [%0], [%1], %2, [%3];"
                    :: "r"(dst), "l"(src), "r"(1024u), "r"(mbB) : "memory");
            }
        }
        {
            const unsigned parity = (unsigned)(t & 1);
            const unsigned mb = (kq4 < 2) ? mbA : mbB;
            asm volatile(
                "{\n\t"
                ".reg .pred P1;\n\t"
                "WAIT_%=:\n\t"
                "mbarrier.try_wait.parity.acquire.cta.shared::cta.b64 P1, [%0], %1, 0x989680;\n\t"
                "@P1 bra.uni DONE_%=;\n\t"
                "bra.uni WAIT_%=;\n\t"
                "DONE_%=:\n\t"
                "}"
                :: "r"(mb), "r"(parity) : "memory");
        }

        u64 acc[4][4];
#pragma unroll
        for (int i = 0; i < 4; ++i)
#pragma unroll
            for (int jj = 0; jj < 4; ++jj) acc[i][jj] = 0ull;

        const float* wsb[4];
        const float* hbb[4];
#pragma unroll
        for (int i = 0; i < 4; ++i) wsb[i] = &Ws[(rg + 8 * i) * WS_STR + kbeg];
#pragma unroll
        for (int jj = 0; jj < 4; ++jj) hbb[jj] = &hall[(bgrp + 16 * jj) * HA_STR + kbeg];

#pragma unroll 4
        for (int kk = 0; kk < 128; kk += 4) {
            ulonglong2 wv[4], hv[4];
#pragma unroll
            for (int i = 0; i < 4; ++i)
                wv[i] = *reinterpret_cast<const ulonglong2*>(wsb[i] + kk);
#pragma unroll
            for (int jj = 0; jj < 4; ++jj)
                hv[jj] = *reinterpret_cast<const ulonglong2*>(hbb[jj] + kk);
#pragma unroll
            for (int i = 0; i < 4; ++i)
#pragma unroll
                for (int jj = 0; jj < 4; ++jj) {
                    ffma2(acc[i][jj], wv[i].x, hv[jj].x);
                    ffma2(acc[i][jj], wv[i].y, hv[jj].y);
                }
        }

        // K-split reduce: quarters 1..3 publish, quarter 0 combines + gates
        if (kq4 != 0) {
            float* rp = &red[((kq4 - 1) * 128 + r) * RED_STR];
#pragma unroll
            for (int i = 0; i < 4; ++i)
#pragma unroll
                for (int jj = 0; jj < 4; ++jj)
                    rp[i * 4 + jj] = f2sum(acc[i][jj]);
        }
        __syncthreads();

        if (kq4 == 0) {
            float* hdst = g_hbuf[t & 1][dir];
            const float* rp0 = &red[(0 * 128 + r) * RED_STR];
            const float* rp1 = &red[(1 * 128 + r) * RED_STR];
            const float* rp2 = &red[(2 * 128 + r) * RED_STR];
#pragma unroll
            for (int jj = 0; jj < 4; ++jj) {
                int b = bgrp + 16 * jj;
                float ig = f2sum(acc[0][jj]) + rp0[0 * 4 + jj] + rp1[0 * 4 + jj] + rp2[0 * 4 + jj] + pf[0][jj];
                float fg = f2sum(acc[1][jj]) + rp0[1 * 4 + jj] + rp1[1 * 4 + jj] + rp2[1 * 4 + jj] + pf[1][jj];
                float gg = f2sum(acc[2][jj]) + rp0[2 * 4 + jj] + rp1[2 * 4 + jj] + rp2[2 * 4 + jj] + pf[2][jj];
                float og = f2sum(acc[3][jj]) + rp0[3 * 4 + jj] + rp1[3 * 4 + jj] + rp2[3 * 4 + jj] + pf[3][jj];
                int L = Lb[jj];
                bool m = (t < L);
                float cn = sigf(fg) * creg[jj] + sigf(ig) * tanhf(gg);
                float hn = sigf(og) * tanhf(cn);
                if (m) { creg[jj] = cn; hreg[jj] = hn; }
                hdst[b * H_ + u] = hreg[jj];
                float outv = m ? hn : 0.0f;
                if (dir == 0) {
                    g_hf[((size_t)b * S_ + t) * H_ + u] = outv;
                } else {
                    int td = m ? (L - 1 - t) : t;
                    g_hb[((size_t)b * S_ + td) * H_ + u] = outv;
                }
            }
        }
        lstm_barrier(dir, grp);
    }
}

// ---------------- K3: classifier logits = [hf,hb] @ Wc^T + bc ---------------
__global__ __launch_bounds__(256) void k_cls(const float* __restrict__ Wc,
                                             const float* __restrict__ bc,
                                             float* __restrict__ out) {
    __shared__ float hs[128 * 68];
    __shared__ float wcs[32 * 68];
    const int m0  = blockIdx.x * 128;    // flattened row = b*S + t
    const int tid = threadIdx.x;
    const int tq  = tid & 7;
    const int rq  = tid >> 3;
    const int tok0 = tq * 4, r0 = rq * 4;

    u64 acc[4][4];
#pragma unroll
    for (int i = 0; i < 4; ++i)
#pragma unroll
        for (int jm = 0; jm < 4; ++jm) acc[i][jm] = 0ull;

    for (int c = 0; c < 16; ++c) {
        __syncthreads();
        const float* src = (c < 8) ? g_hf : g_hb;
        const int kbase = (c & 7) * 64;
#pragma unroll
        for (int e = tid; e < 2048; e += 256) {
            int r = e >> 4, kq = e & 15;
            *reinterpret_cast<float4*>(&hs[r * 68 + kq * 4]) =
                *reinterpret_cast<const float4*>(&src[(size_t)(m0 + r) * 512 + kbase + kq * 4]);
        }
#pragma unroll
        for (int e = tid; e < 512; e += 256) {
            int tok = e >> 4, kq = e & 15;
            float4 v = make_float4(0.f, 0.f, 0.f, 0.f);
            if (tok < T_)
                v = *reinterpret_cast<const float4*>(&Wc[(size_t)tok * 1024 + c * 64 + kq * 4]);
            *reinterpret_cast<float4*>(&wcs[tok * 68 + kq * 4]) = v;
        }
        __syncthreads();
#pragma unroll
        for (int kk = 0; kk < 64; kk += 4) {
            ulonglong2 av[4], bv[4];
#pragma unroll
            for (int i = 0; i < 4; ++i)
                av[i] = *reinterpret_cast<const ulonglong2*>(&hs[(r0 + i) * 68 + kk]);
#pragma unroll
            for (int jm = 0; jm < 4; ++jm)
                bv[jm] = *reinterpret_cast<const ulonglong2*>(&wcs[(tok0 + jm) * 68 + kk]);
#pragma unroll
            for (int i = 0; i < 4; ++i)
#pragma unroll
                for (int jm = 0; jm < 4; ++jm) {
                    ffma2(acc[i][jm], av[i].x, bv[jm].x);
                    ffma2(acc[i][jm], av[i].y, bv[jm].y);
                }
        }
    }
#pragma unroll
    for (int jm = 0; jm < 4; ++jm) {
        int tok = tok0 + jm;
        if (tok < T_) {
            float bcv = bc[tok];
#pragma unroll
            for (int i = 0; i < 4; ++i)
                out[LOGITS_OFF + (size_t)(m0 + r0 + i) * T_ + tok] = f2sum(acc[i][jm]) + bcv;
        }
    }
}

// ---------------- K4: CRF forward (logsumexp), Viterbi, numerator -----------
__global__ __launch_bounds__(32) void k_crf(const float* __restrict__ out_logits,
                                            const int* __restrict__ labels,
                                            const float* __restrict__ trans,
                                            const float* __restrict__ start,
                                            const float* __restrict__ end,
                                            float* __restrict__ out) {
    __shared__ float trans_s[T_ * T_ + 8];
    __shared__ float sc[32], vv[32];
    __shared__ float end_s[T_], start_s[T_];
    __shared__ unsigned char hist[(S_ - 1) * T_];

    const int b = blockIdx.x;
    const int j = threadIdx.x;
    const int jc = (j < T_) ? j : (T_ - 1);
    const int L = g_len[b];
    const float* em = out_logits + LOGITS_OFF + (size_t)b * S_ * T_;
    const int* lab = labels + b * S_;

    for (int e = j; e < T_ * T_; e += 32) trans_s[e] = trans[e];
    if (j < T_) { end_s[j] = end[j]; start_s[j] = start[j]; }
    __syncwarp();

    float score  = (j < T_) ? (start_s[j] + em[j]) : -1e30f;
    float vscore = score;

    for (int t = 1; t < S_; ++t) {
        sc[j] = score; vv[j] = vscore;
        __syncwarp();
        bool m = (t < L);
        float e = (j < T_) ? em[t * T_ + j] : 0.0f;

        float mx = -1e30f;
        float bmax = -1e30f; int bi = 0;
#pragma unroll 5
        for (int i = 0; i < T_; ++i) {
            float tr = trans_s[i * T_ + jc];
            float v1 = sc[i] + tr;
            mx = fmaxf(mx, v1);
            float v2 = vv[i] + tr;
            if (v2 > bmax) { bmax = v2; bi = i; }
        }
        float smv = 0.0f;
#pragma unroll 5
        for (int i = 0; i < T_; ++i) {
            float v1 = sc[i] + trans_s[i * T_ + jc];
            smv += expf(v1 - mx);
        }
        if (j < T_) {
            hist[(t - 1) * T_ + j] = (unsigned char)(m ? bi : j);
            if (m) {
                score  = mx + logf(smv) + e;
                vscore = bmax + e;
            }
        }
        __syncwarp();
    }
    sc[j] = score; vv[j] = vscore;
    __syncwarp();

    float num = 0.0f;
    for (int t = 1 + j; t < S_; t += 32) {
        if (t < L) {
            int at  = lab[t];
            int at1 = lab[t - 1];
            num += trans_s[at1 * T_ + at] + em[t * T_ + at];
        }
    }
#pragma unroll
    for (int o = 16; o; o >>= 1) num += __shfl_xor_sync(0xffffffffu, num, o);

    if (j == 0) {
        int a0 = lab[0];
        num += start_s[a0] + em[a0] + end_s[lab[L - 1]];
        float mx = -1e30f;
        for (int i = 0; i < T_; ++i) mx = fmaxf(mx, sc[i] + end_s[i]);
        float smv = 0.0f;
        for (int i = 0; i < T_; ++i) smv += expf(sc[i] + end_s[i] - mx);
        float denom = mx + logf(smv);
        g_llh[b] = num - denom;

        float best = -1e30f; int tag = 0;
        for (int i = 0; i < T_; ++i) {
            float v = vv[i] + end_s[i];
            if (v > best) { best = v; tag = i; }
        }
        out[TAGS_OFF + b * S_ + (S_ - 1)] = (float)tag;
        for (int t = S_ - 2; t >= 0; --t) {
            if ((t + 1) < L) tag = hist[t * T_ + tag];
            out[TAGS_OFF + b * S_ + t] = (float)tag;
        }
    }
}

// ---------------- K5: loss reduction ----------------------------------------
__global__ void k_loss(float* __restrict__ out) {
    __shared__ float sv[64];
    __shared__ int scn[64];
    int tid = threadIdx.x;
    sv[tid]  = g_llh[tid];
    scn[tid] = g_len[tid];
    __syncthreads();
    if (tid == 0) {
        float s = 0.0f; int n = 0;
        for (int i = 0; i < 64; ++i) { s += sv[i]; n += scn[i]; }
        out[0] = -(s / (float)n);
    }
}

// ---------------- launch -----------------------------------------------------
extern "C" void kernel_launch(void* const* d_in, const int* in_sizes, int n_in,
                              void* d_out, int out_size) {
    const float* x       = (const float*)d_in[0];
    const float* W_ih_f  = (const float*)d_in[1];
    const float* W_hh_f  = (const float*)d_in[2];
    const float* b_f     = (const float*)d_in[3];
    const float* W_ih_b  = (const float*)d_in[4];
    const float* W_hh_b  = (const float*)d_in[5];
    const float* b_b     = (const float*)d_in[6];
    const float* Wc      = (const float*)d_in[7];
    const float* bc      = (const float*)d_in[8];
    const float* c_start = (const float*)d_in[9];
    const float* c_end   = (const float*)d_in[10];
    const float* c_trans = (const float*)d_in[11];
    const int*   amask   = (const int*)d_in[12];
    const int*   labels  = (const int*)d_in[13];
    float* out = (float*)d_out;

    const size_t smem_lstm = (32 * WS_STR + 64 * HA_STR + 384 * RED_STR) * sizeof(float); // ~219 KB
    cudaFuncSetAttribute(k_lstm, cudaFuncAttributeMaxDynamicSharedMemorySize, (int)smem_lstm);

    k_len<<<B_, 256>>>(amask, out);
    k_pre<<<dim3(32, S_, 2), 256>>>(x, W_ih_f, b_f, W_ih_b, b_b);
    k_lstm<<<128, 512, smem_lstm>>>(W_hh_f, W_hh_b);
    k_cls<<<256, 256>>>(Wc, bc, out);
    k_crf<<<B_, 32>>>(out, labels, c_trans, c_start, c_end, out);
    k_loss<<<1, 64>>>(out);
}

// round 15
// speedup vs baseline: 1.0873x; 1.0873x over previous
#include <cuda_runtime.h>
#include <math.h>
#include <stdint.h>

#define B_  64
#define S_  512
#define I_  300
#define H_  512
#define T_  25
#define G4_ 2048

// d_out layout (float32): [loss(1)] [logits B*S*T] [tags B*S] [pred_mask B*S]
#define LOGITS_OFF 1
#define TAGS_OFF   (1 + B_*S_*T_)
#define PM_OFF     (TAGS_OFF + B_*S_)

typedef unsigned long long u64;

// ---------------- device scratch (static, no allocations) -------------------
__device__ float g_pre[(size_t)2 * S_ * B_ * G4_];   // [dir][t][b][g]
__device__ float g_hf[(size_t)B_ * S_ * H_];         // forward outputs
__device__ float g_hb[(size_t)B_ * S_ * H_];         // backward outputs (un-reversed)
__device__ float g_hbuf[2][2][B_ * H_];              // [buf][dir][b*H+u]
__device__ int   g_len[B_];
__device__ float g_llh[B_];

// two-level per-quadrant barrier state (monotonic, replay-safe)
// quadrant q = dir*2 + batch-half (0..3); 4 groups of 8 blocks each
__device__ __align__(128) u64 g_grp[16][16];         // [q*4+grp][0]
__device__ __align__(128) u64 g_mst[4][16];          // [q][0]
__device__ __align__(128) u64 g_rel[4][16];          // [q][0]

// ---------------- packed f32x2 FMA ------------------------------------------
__device__ __forceinline__ void ffma2(u64 &d, u64 a, u64 b) {
    asm("fma.rn.f32x2 %0, %1, %2, %0;" : "+l"(d) : "l"(a), "l"(b));
}
__device__ __forceinline__ float f2sum(u64 v) {
    float lo = __uint_as_float((unsigned)(v & 0xffffffffu));
    float hi = __uint_as_float((unsigned)(v >> 32));
    return lo + hi;
}

// ---------------- two-level barrier: 32 blocks of one quadrant --------------
__device__ __forceinline__ void lstm_barrier(int q, int grp) {
    __syncthreads();
    if (threadIdx.x == 0) {
        __threadfence();
        u64 tk = atomicAdd(&g_grp[q * 4 + grp][0], 1ull);
        u64 round = tk >> 3;                       // 8 arrivals per group
        if ((tk & 7ull) == 7ull) {
            u64 t2 = atomicAdd(&g_mst[q][0], 1ull);
            if ((t2 & 3ull) == 3ull) {             // 4 groups per quadrant
                u64 rel = (t2 >> 2) + 1ull;
                asm volatile("st.release.gpu.global.u64 [%0], %1;"
                             :: "l"(&g_rel[q][0]), "l"(rel) : "memory");
            }
        }
        u64 target = round + 1ull;
        u64 v;
        do {
            asm volatile("ld.acquire.gpu.global.u64 %0, [%1];"
                         : "=l"(v) : "l"(&g_rel[q][0]) : "memory");
        } while (v < target);
    }
    __syncthreads();
}

__device__ __forceinline__ float sigf(float x) { return 1.0f / (1.0f + expf(-x)); }

// ---------------- K0: lengths + pred_mask -----------------------------------
__global__ void k_len(const int* __restrict__ mask, float* __restrict__ out) {
    __shared__ int sred[256];
    int b = blockIdx.x;
    int s = 0;
    for (int t = threadIdx.x; t < S_; t += 256) s += mask[b * S_ + t];
    sred[threadIdx.x] = s;
    __syncthreads();
    for (int o = 128; o > 0; o >>= 1) {
        if (threadIdx.x < o) sred[threadIdx.x] += sred[threadIdx.x + o];
        __syncthreads();
    }
    int L = sred[0];
    if (threadIdx.x == 0) g_len[b] = L;
    for (int t = threadIdx.x; t < S_; t += 256)
        out[PM_OFF + b * S_ + t] = (t < L) ? 1.0f : 0.0f;
}

// ---------------- K1: pre-activations x@W_ih^T + b --------------------------
#define KC1 20
__global__ __launch_bounds__(256) void k_pre(const float* __restrict__ x,
                                             const float* __restrict__ Wf,
                                             const float* __restrict__ bf,
                                             const float* __restrict__ Wb,
                                             const float* __restrict__ bb) {
    __shared__ float As[64 * KC1];   // [b][k]
    __shared__ float Bs[64 * KC1];   // [g][k]
    const int gc  = blockIdx.x;
    const int t   = blockIdx.y;
    const int dir = blockIdx.z;
    const float* W    = dir ? Wb : Wf;
    const float* bias = dir ? bb : bf;
    const int g0  = gc * 64;
    const int tid = threadIdx.x;
    const int gg  = tid & 15;
    const int bb_ = tid >> 4;

    int ib[5], ik[5];
    const float* srcA[5];
    const float* srcB[5];
#pragma unroll
    for (int it = 0; it < 5; ++it) {
        int e = tid + 256 * it;
        ib[it] = e / KC1;
        ik[it] = e - ib[it] * KC1;
        int b = ib[it];
        int L = g_len[b];
        int tt = t;
        if (dir && t < L) tt = L - 1 - t;
        srcA[it] = &x[((size_t)b * S_ + tt) * I_ + ik[it]];
        srcB[it] = &W[(size_t)(g0 + b) * I_ + ik[it]];
    }

    float rA[5], rB[5];
#pragma unroll
    for (int it = 0; it < 5; ++it) { rA[it] = srcA[it][0]; rB[it] = srcB[it][0]; }

    u64 acc[4][4];
#pragma unroll
    for (int i = 0; i < 4; ++i)
#pragma unroll
        for (int j = 0; j < 4; ++j) acc[i][j] = 0ull;

    for (int c = 0; c < 15; ++c) {
#pragma unroll
        for (int it = 0; it < 5; ++it) {
            As[ib[it] * KC1 + ik[it]] = rA[it];
            Bs[ib[it] * KC1 + ik[it]] = rB[it];
        }
        __syncthreads();
        if (c < 14) {
            const int k0 = (c + 1) * KC1;
#pragma unroll
            for (int it = 0; it < 5; ++it) { rA[it] = srcA[it][k0]; rB[it] = srcB[it][k0]; }
        }
#pragma unroll
        for (int kq = 0; kq < KC1 / 4; ++kq) {
            ulonglong2 av[4], bv[4];
#pragma unroll
            for (int jj = 0; jj < 4; ++jj)
                av[jj] = *reinterpret_cast<const ulonglong2*>(&As[(bb_ + 16 * jj) * KC1 + kq * 4]);
#pragma unroll
            for (int i = 0; i < 4; ++i)
                bv[i] = *reinterpret_cast<const ulonglong2*>(&Bs[(gg + 16 * i) * KC1 + kq * 4]);
#pragma unroll
            for (int i = 0; i < 4; ++i)
#pragma unroll
                for (int jj = 0; jj < 4; ++jj) {
                    ffma2(acc[i][jj], av[jj].x, bv[i].x);
                    ffma2(acc[i][jj], av[jj].y, bv[i].y);
                }
        }
        __syncthreads();
    }
#pragma unroll
    for (int i = 0; i < 4; ++i) {
        int g = g0 + gg + 16 * i;
        float bv = bias[g];
#pragma unroll
        for (int jj = 0; jj < 4; ++jj) {
            int b = bb_ + 16 * jj;
            g_pre[(((size_t)dir * S_ + t) * B_ + b) * G4_ + g] = f2sum(acc[i][jj]) + bv;
        }
    }
}

// ---------------- K2: persistent bidirectional LSTM scan --------------------
// 128 blocks x 256 threads. Block j: dir=j>>6, bh=(j>>5)&1, ug=j&31, u0=ug*16.
// Four independent quadrants (dir,bh) of 32 blocks; barrier spans 32 blocks.
// Thread: kh = tid>>7 (K half); r = tid&127: rg = r&15 (unit), bgrp = r>>4 (0..7).
// Micro-tile: 4 gates x 4 batches (b = bh*32 + bgrp + 8*jj) over K-half.
// SMEM: Ws[64][516] W_hh rows (16 units x 4 gates); hall[32][516]; red[128][17].
#define WS_STR 516
#define HA_STR 516
#define RED_STR 17
__global__ __launch_bounds__(256) void k_lstm(const float* __restrict__ Whf,
                                              const float* __restrict__ Whb) {
    extern __shared__ float sm[];
    float* Ws   = sm;                               // 64*516
    float* hall = sm + 64 * WS_STR;                 // 32*516
    float* red  = sm + 64 * WS_STR + 32 * HA_STR;   // 128*17
    __shared__ __align__(8) u64 mbar;

    const int j    = blockIdx.x;
    const int dir  = j >> 6;
    const int bh   = (j >> 5) & 1;      // batch half
    const int q    = dir * 2 + bh;      // quadrant
    const int grp  = (j & 31) >> 3;     // barrier group 0..3 within quadrant
    const int u0   = (j & 31) * 16;
    const int tid  = threadIdx.x;
    const int kh   = tid >> 7;          // K-split half
    const int r    = tid & 127;
    const int rg   = r & 15;            // hidden-unit within slice (0..15)
    const int bgrp = r >> 4;            // 0..7 ; b = bh*32 + bgrp + 8*jj
    const int u    = u0 + rg;
    const int kbeg = kh << 8;           // 0 or 256
    const int b0   = bh * 32;

    const float* Wh = dir ? Whb : Whf;
    const unsigned hall_s = (unsigned)__cvta_generic_to_shared(hall);
    const unsigned mb     = (unsigned)__cvta_generic_to_shared(&mbar);

    if (tid == 0) {
        asm volatile("mbarrier.init.shared.b64 [%0], 1;" :: "r"(mb) : "memory");
    }

    // load persistent W slice: row rr (0..63) -> W_hh[(rr>>4)*512 + u0 + (rr&15)][k]
    for (int e = tid; e < 64 * 512; e += 256) {
        int rr = e >> 9, k = e & 511;
        int grow = (rr >> 4) * H_ + u0 + (rr & 15);
        Ws[rr * WS_STR + k] = Wh[(size_t)grow * H_ + k];
    }
    // zero read-buffer (buf 1) for our slice (32 batches x 16 units)
    for (int e = tid; e < 32 * 16; e += 256) {
        int b = e >> 4, uu = e & 15;
        g_hbuf[1][dir][(b0 + b) * H_ + u0 + uu] = 0.0f;
    }

    float creg[4] = {0.f, 0.f, 0.f, 0.f};
    float hreg[4] = {0.f, 0.f, 0.f, 0.f};
    int Lb[4];
#pragma unroll
    for (int jj = 0; jj < 4; ++jj) Lb[jj] = g_len[b0 + bgrp + 8 * jj];

    lstm_barrier(q, grp);

    for (int t = 0; t < S_; ++t) {
        const float* hsrc = g_hbuf[(t & 1) ^ 1][dir];

        // prefetch pre-activation gates early (DRAM latency hides under staging+k-loop)
        float pf[4][4];
        if (kh == 0) {
            const float* pbase = &g_pre[(((size_t)dir * S_ + t) * B_) * G4_];
#pragma unroll
            for (int jj = 0; jj < 4; ++jj) {
                const float* p = pbase + (size_t)(b0 + bgrp + 8 * jj) * G4_ + u;
                pf[0][jj] = p[0];
                pf[1][jj] = p[512];
                pf[2][jj] = p[1024];
                pf[3][jj] = p[1536];
            }
        }

        // stage h tile (32 rows x 2KB) via TMA bulk copies into padded rows
        if (tid == 0) {
            asm volatile("mbarrier.arrive.expect_tx.shared.b64 _, [%0], %1;"
                         :: "r"(mb), "r"(32u * 2048u) : "memory");
#pragma unroll 4
            for (int b = 0; b < 32; ++b) {
                unsigned dst = hall_s + (unsigned)(b * HA_STR * 4);
                const float* src = hsrc + (b0 + b) * 512;
                asm volatile(
                    "cp.async.bulk.shared::cta.global.mbarrier::complete_tx::bytes [%0], [%1], %2, [%3];"
                    :: "r"(dst), "l"(src), "r"(2048u), "r"(mb) : "memory");
            }
        }
        {
            const unsigned parity = (unsigned)(t & 1);
            asm volatile(
                "{\n\t"
                ".reg .pred P1;\n\t"
                "WAIT_%=:\n\t"
                "mbarrier.try_wait.parity.acquire.cta.shared::cta.b64 P1, [%0], %1, 0x989680;\n\t"
                "@P1 bra.uni DONE_%=;\n\t"
                "bra.uni WAIT_%=;\n\t"
                "DONE_%=:\n\t"
                "}"
                :: "r"(mb), "r"(parity) : "memory");
        }

        u64 acc[4][4];
#pragma unroll
        for (int i = 0; i < 4; ++i)
#pragma unroll
            for (int jj = 0; jj < 4; ++jj) acc[i][jj] = 0ull;

        const float* wsb[4];
        const float* hbb[4];
#pragma unroll
        for (int i = 0; i < 4; ++i) wsb[i] = &Ws[(rg + 16 * i) * WS_STR + kbeg];
#pragma unroll
        for (int jj = 0; jj < 4; ++jj) hbb[jj] = &hall[(bgrp + 8 * jj) * HA_STR + kbeg];

#pragma unroll 4
        for (int kk = 0; kk < 256; kk += 4) {
            ulonglong2 wv[4], hv[4];
#pragma unroll
            for (int i = 0; i < 4; ++i)
                wv[i] = *reinterpret_cast<const ulonglong2*>(wsb[i] + kk);
#pragma unroll
            for (int jj = 0; jj < 4; ++jj)
                hv[jj] = *reinterpret_cast<const ulonglong2*>(hbb[jj] + kk);
#pragma unroll
            for (int i = 0; i < 4; ++i)
#pragma unroll
                for (int jj = 0; jj < 4; ++jj) {
                    ffma2(acc[i][jj], wv[i].x, hv[jj].x);
                    ffma2(acc[i][jj], wv[i].y, hv[jj].y);
                }
        }

        // K-split reduce: half 1 publishes, half 0 combines + gates
        if (kh == 1) {
            float* rp = &red[r * RED_STR];
#pragma unroll
            for (int i = 0; i < 4; ++i)
#pragma unroll
                for (int jj = 0; jj < 4; ++jj)
                    rp[i * 4 + jj] = f2sum(acc[i][jj]);
        }
        __syncthreads();

        if (kh == 0) {
            float* hdst = g_hbuf[t & 1][dir];
            const float* rp = &red[r * RED_STR];
#pragma unroll
            for (int jj = 0; jj < 4; ++jj) {
                int b = b0 + bgrp + 8 * jj;
                float ig = f2sum(acc[0][jj]) + rp[0 * 4 + jj] + pf[0][jj];
                float fg = f2sum(acc[1][jj]) + rp[1 * 4 + jj] + pf[1][jj];
                float gg = f2sum(acc[2][jj]) + rp[2 * 4 + jj] + pf[2][jj];
                float og = f2sum(acc[3][jj]) + rp[3 * 4 + jj] + pf[3][jj];
                int L = Lb[jj];
                bool m = (t < L);
                float cn = sigf(fg) * creg[jj] + sigf(ig) * tanhf(gg);
                float hn = sigf(og) * tanhf(cn);
                if (m) { creg[jj] = cn; hreg[jj] = hn; }
                hdst[b * H_ + u] = hreg[jj];
                float outv = m ? hn : 0.0f;
                if (dir == 0) {
                    g_hf[((size_t)b * S_ + t) * H_ + u] = outv;
                } else {
                    int td = m ? (L - 1 - t) : t;
                    g_hb[((size_t)b * S_ + td) * H_ + u] = outv;
                }
            }
        }
        lstm_barrier(q, grp);
    }
}

// ---------------- K3: classifier logits = [hf,hb] @ Wc^T + bc ---------------
__global__ __launch_bounds__(256) void k_cls(const float* __restrict__ Wc,
                                             const float* __restrict__ bc,
                                             float* __restrict__ out) {
    __shared__ float hs[128 * 68];
    __shared__ float wcs[32 * 68];
    const int m0  = blockIdx.x * 128;    // flattened row = b*S + t
    const int tid = threadIdx.x;
    const int tq  = tid & 7;
    const int rq  = tid >> 3;
    const int tok0 = tq * 4, r0 = rq * 4;

    u64 acc[4][4];
#pragma unroll
    for (int i = 0; i < 4; ++i)
#pragma unroll
        for (int jm = 0; jm < 4; ++jm) acc[i][jm] = 0ull;

    for (int c = 0; c < 16; ++c) {
        __syncthreads();
        const float* src = (c < 8) ? g_hf : g_hb;
        const int kbase = (c & 7) * 64;
#pragma unroll
        for (int e = tid; e < 2048; e += 256) {
            int r = e >> 4, kq = e & 15;
            *reinterpret_cast<float4*>(&hs[r * 68 + kq * 4]) =
                *reinterpret_cast<const float4*>(&src[(size_t)(m0 + r) * 512 + kbase + kq * 4]);
        }
#pragma unroll
        for (int e = tid; e < 512; e += 256) {
            int tok = e >> 4, kq = e & 15;
            float4 v = make_float4(0.f, 0.f, 0.f, 0.f);
            if (tok < T_)
                v = *reinterpret_cast<const float4*>(&Wc[(size_t)tok * 1024 + c * 64 + kq * 4]);
            *reinterpret_cast<float4*>(&wcs[tok * 68 + kq * 4]) = v;
        }
        __syncthreads();
#pragma unroll
        for (int kk = 0; kk < 64; kk += 4) {
            ulonglong2 av[4], bv[4];
#pragma unroll
            for (int i = 0; i < 4; ++i)
                av[i] = *reinterpret_cast<const ulonglong2*>(&hs[(r0 + i) * 68 + kk]);
#pragma unroll
            for (int jm = 0; jm < 4; ++jm)
                bv[jm] = *reinterpret_cast<const ulonglong2*>(&wcs[(tok0 + jm) * 68 + kk]);
#pragma unroll
            for (int i = 0; i < 4; ++i)
#pragma unroll
                for (int jm = 0; jm < 4; ++jm) {
                    ffma2(acc[i][jm], av[i].x, bv[jm].x);
                    ffma2(acc[i][jm], av[i].y, bv[jm].y);
                }
        }
    }
#pragma unroll
    for (int jm = 0; jm < 4; ++jm) {
        int tok = tok0 + jm;
        if (tok < T_) {
            float bcv = bc[tok];
#pragma unroll
            for (int i = 0; i < 4; ++i)
                out[LOGITS_OFF + (size_t)(m0 + r0 + i) * T_ + tok] = f2sum(acc[i][jm]) + bcv;
        }
    }
}

// ---------------- K4: CRF forward (logsumexp), Viterbi, numerator -----------
__global__ __launch_bounds__(32) void k_crf(const float* __restrict__ out_logits,
                                            const int* __restrict__ labels,
                                            const float* __restrict__ trans,
                                            const float* __restrict__ start,
                                            const float* __restrict__ end,
                                            float* __restrict__ out) {
    __shared__ float trans_s[T_ * T_ + 8];
    __shared__ float sc[32], vv[32];
    __shared__ float end_s[T_], start_s[T_];
    __shared__ unsigned char hist[(S_ - 1) * T_];

    const int b = blockIdx.x;
    const int j = threadIdx.x;
    const int jc = (j < T_) ? j : (T_ - 1);
    const int L = g_len[b];
    const float* em = out_logits + LOGITS_OFF + (size_t)b * S_ * T_;
    const int* lab = labels + b * S_;

    for (int e = j; e < T_ * T_; e += 32) trans_s[e] = trans[e];
    if (j < T_) { end_s[j] = end[j]; start_s[j] = start[j]; }
    __syncwarp();

    float score  = (j < T_) ? (start_s[j] + em[j]) : -1e30f;
    float vscore = score;

    for (int t = 1; t < S_; ++t) {
        sc[j] = score; vv[j] = vscore;
        __syncwarp();
        bool m = (t < L);
        float e = (j < T_) ? em[t * T_ + j] : 0.0f;

        float mx = -1e30f;
        float bmax = -1e30f; int bi = 0;
#pragma unroll 5
        for (int i = 0; i < T_; ++i) {
            float tr = trans_s[i * T_ + jc];
            float v1 = sc[i] + tr;
            mx = fmaxf(mx, v1);
            float v2 = vv[i] + tr;
            if (v2 > bmax) { bmax = v2; bi = i; }
        }
        float smv = 0.0f;
#pragma unroll 5
        for (int i = 0; i < T_; ++i) {
            float v1 = sc[i] + trans_s[i * T_ + jc];
            smv += expf(v1 - mx);
        }
        if (j < T_) {
            hist[(t - 1) * T_ + j] = (unsigned char)(m ? bi : j);
            if (m) {
                score  = mx + logf(smv) + e;
                vscore = bmax + e;
            }
        }
        __syncwarp();
    }
    sc[j] = score; vv[j] = vscore;
    __syncwarp();

    float num = 0.0f;
    for (int t = 1 + j; t < S_; t += 32) {
        if (t < L) {
            int at  = lab[t];
            int at1 = lab[t - 1];
            num += trans_s[at1 * T_ + at] + em[t * T_ + at];
        }
    }
#pragma unroll
    for (int o = 16; o; o >>= 1) num += __shfl_xor_sync(0xffffffffu, num, o);

    if (j == 0) {
        int a0 = lab[0];
        num += start_s[a0] + em[a0] + end_s[lab[L - 1]];
        float mx = -1e30f;
        for (int i = 0; i < T_; ++i) mx = fmaxf(mx, sc[i] + end_s[i]);
        float smv = 0.0f;
        for (int i = 0; i < T_; ++i) smv += expf(sc[i] + end_s[i] - mx);
        float denom = mx + logf(smv);
        g_llh[b] = num - denom;

        float best = -1e30f; int tag = 0;
        for (int i = 0; i < T_; ++i) {
            float v = vv[i] + end_s[i];
            if (v > best) { best = v; tag = i; }
        }
        out[TAGS_OFF + b * S_ + (S_ - 1)] = (float)tag;
        for (int t = S_ - 2; t >= 0; --t) {
            if ((t + 1) < L) tag = hist[t * T_ + tag];
            out[TAGS_OFF + b * S_ + t] = (float)tag;
        }
    }
}

// ---------------- K5: loss reduction ----------------------------------------
__global__ void k_loss(float* __restrict__ out) {
    __shared__ float sv[64];
    __shared__ int scn[64];
    int tid = threadIdx.x;
    sv[tid]  = g_llh[tid];
    scn[tid] = g_len[tid];
    __syncthreads();
    if (tid == 0) {
        float s = 0.0f; int n = 0;
        for (int i = 0; i < 64; ++i) { s += sv[i]; n += scn[i]; }
        out[0] = -(s / (float)n);
    }
}

// ---------------- launch -----------------------------------------------------
extern "C" void kernel_launch(void* const* d_in, const int* in_sizes, int n_in,
                              void* d_out, int out_size) {
    const float* x       = (const float*)d_in[0];
    const float* W_ih_f  = (const float*)d_in[1];
    const float* W_hh_f  = (const float*)d_in[2];
    const float* b_f     = (const float*)d_in[3];
    const float* W_ih_b  = (const float*)d_in[4];
    const float* W_hh_b  = (const float*)d_in[5];
    const float* b_b     = (const float*)d_in[6];
    const float* Wc      = (const float*)d_in[7];
    const float* bc      = (const float*)d_in[8];
    const float* c_start = (const float*)d_in[9];
    const float* c_end   = (const float*)d_in[10];
    const float* c_trans = (const float*)d_in[11];
    const int*   amask   = (const int*)d_in[12];
    const int*   labels  = (const int*)d_in[13];
    float* out = (float*)d_out;

    const size_t smem_lstm = (64 * WS_STR + 32 * HA_STR + 128 * RED_STR) * sizeof(float); // ~207 KB
    cudaFuncSetAttribute(k_lstm, cudaFuncAttributeMaxDynamicSharedMemorySize, (int)smem_lstm);

    k_len<<<B_, 256>>>(amask, out);
    k_pre<<<dim3(32, S_, 2), 256>>>(x, W_ih_f, b_f, W_ih_b, b_b);
    k_lstm<<<128, 256, smem_lstm>>>(W_hh_f, W_hh_b);
    k_cls<<<256, 256>>>(Wc, bc, out);
    k_crf<<<B_, 32>>>(out, labels, c_trans, c_start, c_end, out);
    k_loss<<<1, 64>>>(out);
}

// round 17
// speedup vs baseline: 1.2527x; 1.1521x over previous
#include <cuda_runtime.h>
#include <cuda_bf16.h>
#include <mma.h>
#include <math.h>
#include <stdint.h>

using namespace nvcuda;

#define B_  64
#define S_  512
#define I_  300
#define H_  512
#define T_  25
#define G4_ 2048
#define KP_ 320
#define NROW_ (B_ * S_)

// d_out layout (float32): [loss(1)] [logits B*S*T] [tags B*S] [pred_mask B*S]
#define LOGITS_OFF 1
#define TAGS_OFF   (1 + B_*S_*T_)
#define PM_OFF     (TAGS_OFF + B_*S_)

typedef unsigned long long u64;

// ---------------- device scratch (static, no allocations) -------------------
__device__ float g_pre[(size_t)NROW_ * 4096];        // [row=b*512+s][dir*2048+g]
__device__ float g_hf[(size_t)B_ * S_ * H_];
__device__ float g_hb[(size_t)B_ * S_ * H_];
__device__ float g_hbuf[2][2][B_ * H_];
__device__ int   g_len[B_];
__device__ float g_llh[B_];
__device__ __nv_bfloat16 g_xhi[(size_t)NROW_ * KP_];
__device__ __nv_bfloat16 g_xlo[(size_t)NROW_ * KP_];
__device__ __nv_bfloat16 g_whi[(size_t)4096 * KP_];
__device__ __nv_bfloat16 g_wlo[(size_t)4096 * KP_];

// two-level per-quadrant barrier state (monotonic, replay-safe)
__device__ __align__(128) u64 g_grp[16][16];
__device__ __align__(128) u64 g_mst[4][16];
__device__ __align__(128) u64 g_rel[4][16];

// ---------------- packed f32x2 FMA ------------------------------------------
__device__ __forceinline__ void ffma2(u64 &d, u64 a, u64 b) {
    asm("fma.rn.f32x2 %0, %1, %2, %0;" : "+l"(d) : "l"(a), "l"(b));
}
__device__ __forceinline__ float f2sum(u64 v) {
    float lo = __uint_as_float((unsigned)(v & 0xffffffffu));
    float hi = __uint_as_float((unsigned)(v >> 32));
    return lo + hi;
}

// ---------------- two-level barrier: 32 blocks of one quadrant --------------
__device__ __forceinline__ void lstm_barrier(int q, int grp) {
    __syncthreads();
    if (threadIdx.x == 0) {
        __threadfence();
        u64 tk = atomicAdd(&g_grp[q * 4 + grp][0], 1ull);
        u64 round = tk >> 3;
        if ((tk & 7ull) == 7ull) {
            u64 t2 = atomicAdd(&g_mst[q][0], 1ull);
            if ((t2 & 3ull) == 3ull) {
                u64 rel = (t2 >> 2) + 1ull;
                asm volatile("st.release.gpu.global.u64 [%0], %1;"
                             :: "l"(&g_rel[q][0]), "l"(rel) : "memory");
            }
        }
        u64 target = round + 1ull;
        u64 v;
        do {
            asm volatile("ld.acquire.gpu.global.u64 %0, [%1];"
                         : "=l"(v) : "l"(&g_rel[q][0]) : "memory");
        } while (v < target);
    }
    __syncthreads();
}

__device__ __forceinline__ float sigf(float x) { return 1.0f / (1.0f + expf(-x)); }

// ---------------- K0: lengths + pred_mask -----------------------------------
__global__ void k_len(const int* __restrict__ mask, float* __restrict__ out) {
    __shared__ int sred[256];
    int b = blockIdx.x;
    int s = 0;
    for (int t = threadIdx.x; t < S_; t += 256) s += mask[b * S_ + t];
    sred[threadIdx.x] = s;
    __syncthreads();
    for (int o = 128; o > 0; o >>= 1) {
        if (threadIdx.x < o) sred[threadIdx.x] += sred[threadIdx.x + o];
        __syncthreads();
    }
    int L = sred[0];
    if (threadIdx.x == 0) g_len[b] = L;
    for (int t = threadIdx.x; t < S_; t += 256)
        out[PM_OFF + b * S_ + t] = (t < L) ? 1.0f : 0.0f;
}

// ---------------- K0b: bf16 hi/lo conversion of X and W ---------------------
__global__ __launch_bounds__(256) void k_cvt(const float* __restrict__ x,
                                             const float* __restrict__ Wf,
                                             const float* __restrict__ Wb) {
    int idx = blockIdx.x * 256 + threadIdx.x;       // row*40 + slot
    int row = idx / 40;
    int slot = idx - row * 40;
    if (row >= NROW_ + 4096) return;
    int k0 = slot * 8;
    const float* src;
    __nv_bfloat16 *dhi, *dlo;
    size_t obase;
    if (row < NROW_) {
        src = x + (size_t)row * I_;
        dhi = g_xhi; dlo = g_xlo; obase = (size_t)row * KP_;
    } else {
        int g = row - NROW_;
        src = (g < 2048) ? (Wf + (size_t)g * I_) : (Wb + (size_t)(g - 2048) * I_);
        dhi = g_whi; dlo = g_wlo; obase = (size_t)(row - NROW_) * KP_;
    }
#pragma unroll
    for (int j = 0; j < 8; ++j) {
        int k = k0 + j;
        float v = (k < I_) ? src[k] : 0.0f;
        __nv_bfloat16 hi = __float2bfloat16(v);
        __nv_bfloat16 lo = __float2bfloat16(v - __bfloat162float(hi));
        dhi[obase + k] = hi;
        dlo[obase + k] = lo;
    }
}

// ---------------- K1: pre-activations via WMMA bf16 3-term ------------------
// C[row 128][g 128] = X[row,K] . W[g,K];  K=320 in 5 chunks of 64.
#define BM 128
#define BN 128
#define KC 64
#define XLD 72
#define SM_PRE_BYTES (4 * BM * XLD * 2)   // 73728
__global__ __launch_bounds__(256) void k_pre(const float* __restrict__ bf,
                                             const float* __restrict__ bb) {
    extern __shared__ char smc[];
    __nv_bfloat16* Xhi = (__nv_bfloat16*)smc;           // 128*72
    __nv_bfloat16* Xlo = Xhi + BM * XLD;
    __nv_bfloat16* Whi = Xlo + BM * XLD;
    __nv_bfloat16* Wlo = Whi + BN * XLD;
    float* Cs = (float*)smc;                            // reused after k-loop

    const int m0  = blockIdx.x * BM;
    const int g0  = blockIdx.y * BN;
    const int tid = threadIdx.x;
    const int wid = tid >> 5;
    const int wm  = (wid >> 1) * 32;   // 4 warps in M
    const int wn  = (wid & 1) * 64;    // 2 warps in N

    wmma::fragment<wmma::accumulator, 16, 16, 16, float> acc[2][4];
#pragma unroll
    for (int i = 0; i < 2; ++i)
#pragma unroll
        for (int j = 0; j < 4; ++j) wmma::fill_fragment(acc[i][j], 0.0f);

    for (int c = 0; c < 5; ++c) {
        const int kc = c * KC;
        __syncthreads();
#pragma unroll
        for (int e = tid; e < BM * KC / 4; e += 256) {
            int r = e >> 4, q = (e & 15) * 4;
            *(u64*)&Xhi[r * XLD + q] = *(const u64*)&g_xhi[(size_t)(m0 + r) * KP_ + kc + q];
            *(u64*)&Xlo[r * XLD + q] = *(const u64*)&g_xlo[(size_t)(m0 + r) * KP_ + kc + q];
            *(u64*)&Whi[r * XLD + q] = *(const u64*)&g_whi[(size_t)(g0 + r) * KP_ + kc + q];
            *(u64*)&Wlo[r * XLD + q] = *(const u64*)&g_wlo[(size_t)(g0 + r) * KP_ + kc + q];
        }
        __syncthreads();
#pragma unroll
        for (int ks = 0; ks < 4; ++ks) {
            wmma::fragment<wmma::matrix_a, 16, 16, 16, __nv_bfloat16, wmma::row_major> ahi[2], alo[2];
            wmma::fragment<wmma::matrix_b, 16, 16, 16, __nv_bfloat16, wmma::col_major> bhi[4], blo[4];
#pragma unroll
            for (int i = 0; i < 2; ++i) {
                wmma::load_matrix_sync(ahi[i], Xhi + (wm + i * 16) * XLD + ks * 16, XLD);
                wmma::load_matrix_sync(alo[i], Xlo + (wm + i * 16) * XLD + ks * 16, XLD);
            }
#pragma unroll
            for (int j = 0; j < 4; ++j) {
                wmma::load_matrix_sync(bhi[j], Whi + (wn + j * 16) * XLD + ks * 16, XLD);
                wmma::load_matrix_sync(blo[j], Wlo + (wn + j * 16) * XLD + ks * 16, XLD);
            }
#pragma unroll
            for (int i = 0; i < 2; ++i)
#pragma unroll
                for (int j = 0; j < 4; ++j) {
                    wmma::mma_sync(acc[i][j], ahi[i], bhi[j], acc[i][j]);
                    wmma::mma_sync(acc[i][j], ahi[i], blo[j], acc[i][j]);
                    wmma::mma_sync(acc[i][j], alo[i], bhi[j], acc[i][j]);
                }
        }
    }
    __syncthreads();
#pragma unroll
    for (int i = 0; i < 2; ++i)
#pragma unroll
        for (int j = 0; j < 4; ++j)
            wmma::store_matrix_sync(Cs + (wm + i * 16) * BN + (wn + j * 16),
                                    acc[i][j], BN, wmma::mem_row_major);
    __syncthreads();
#pragma unroll
    for (int e = tid; e < BM * BN; e += 256) {
        int r = e >> 7, cc = e & 127;
        int g = g0 + cc;
        float bias = (g < 2048) ? bf[g] : bb[g - 2048];
        g_pre[(size_t)(m0 + r) * 4096 + g] = Cs[r * BN + cc] + bias;
    }
}

// ---------------- K2: persistent bidirectional LSTM scan --------------------
#define WS_STR 516
#define HA_STR 516
#define RED_STR 17
__global__ __launch_bounds__(256) void k_lstm(const float* __restrict__ Whf,
                                              const float* __restrict__ Whb) {
    extern __shared__ float smf[];
    float* Ws   = smf;
    float* hall = smf + 64 * WS_STR;
    float* red  = smf + 64 * WS_STR + 32 * HA_STR;
    __shared__ __align__(8) u64 mbar;

    const int j    = blockIdx.x;
    const int dir  = j >> 6;
    const int bh   = (j >> 5) & 1;
    const int q    = dir * 2 + bh;
    const int grp  = (j & 31) >> 3;
    const int u0   = (j & 31) * 16;
    const int tid  = threadIdx.x;
    const int kh   = tid >> 7;
    const int r    = tid & 127;
    const int rg   = r & 15;
    const int bgrp = r >> 4;
    const int u    = u0 + rg;
    const int kbeg = kh << 8;
    const int b0   = bh * 32;

    const float* Wh = dir ? Whb : Whf;
    const unsigned hall_s = (unsigned)__cvta_generic_to_shared(hall);
    const unsigned mb     = (unsigned)__cvta_generic_to_shared(&mbar);

    if (tid == 0) {
        asm volatile("mbarrier.init.shared.b64 [%0], 1;" :: "r"(mb) : "memory");
    }

    for (int e = tid; e < 64 * 512; e += 256) {
        int rr = e >> 9, k = e & 511;
        int grow = (rr >> 4) * H_ + u0 + (rr & 15);
        Ws[rr * WS_STR + k] = Wh[(size_t)grow * H_ + k];
    }
    for (int e = tid; e < 32 * 16; e += 256) {
        int b = e >> 4, uu = e & 15;
        g_hbuf[1][dir][(b0 + b) * H_ + u0 + uu] = 0.0f;
    }

    float creg[4] = {0.f, 0.f, 0.f, 0.f};
    float hreg[4] = {0.f, 0.f, 0.f, 0.f};
    int Lb[4];
#pragma unroll
    for (int jj = 0; jj < 4; ++jj) Lb[jj] = g_len[b0 + bgrp + 8 * jj];

    lstm_barrier(q, grp);

    for (int t = 0; t < S_; ++t) {
        const float* hsrc = g_hbuf[(t & 1) ^ 1][dir];

        // gate prefetch: g_pre[row=b*512+tt][dir*2048 + gate*512 + u]
        float pf[4][4];
        if (kh == 0) {
#pragma unroll
            for (int jj = 0; jj < 4; ++jj) {
                int b = b0 + bgrp + 8 * jj;
                int L = Lb[jj];
                int tt = t;
                if (dir && t < L) tt = L - 1 - t;
                const float* p = &g_pre[((size_t)b * 512 + tt) * 4096 + dir * 2048 + u];
                pf[0][jj] = p[0];
                pf[1][jj] = p[512];
                pf[2][jj] = p[1024];
                pf[3][jj] = p[1536];
            }
        }

        if (tid == 0) {
            asm volatile("mbarrier.arrive.expect_tx.shared.b64 _, [%0], %1;"
                         :: "r"(mb), "r"(32u * 2048u) : "memory");
#pragma unroll 4
            for (int b = 0; b < 32; ++b) {
                unsigned dst = hall_s + (unsigned)(b * HA_STR * 4);
                const float* src = hsrc + (b0 + b) * 512;
                asm volatile(
                    "cp.async.bulk.shared::cta.global.mbarrier::complete_tx::bytes [%0], [%1], %2, [%3];"
                    :: "r"(dst), "l"(src), "r"(2048u), "r"(mb) : "memory");
            }
        }
        {
            const unsigned parity = (unsigned)(t & 1);
            asm volatile(
                "{\n\t.reg .pred P1;\n\t"
                "WAIT_%=:\n\t"
                "mbarrier.try_wait.parity.acquire.cta.shared::cta.b64 P1, [%0], %1, 0x989680;\n\t"
                "@P1 bra.uni DONE_%=;\n\t"
                "bra.uni WAIT_%=;\n\t"
                "DONE_%=:\n\t}"
                :: "r"(mb), "r"(parity) : "memory");
        }

        u64 acc[4][4];
#pragma unroll
        for (int i = 0; i < 4; ++i)
#pragma unroll
            for (int jj = 0; jj < 4; ++jj) acc[i][jj] = 0ull;

        const float* wsb[4];
        const float* hbb[4];
#pragma unroll
        for (int i = 0; i < 4; ++i) wsb[i] = &Ws[(rg + 16 * i) * WS_STR + kbeg];
#pragma unroll
        for (int jj = 0; jj < 4; ++jj) hbb[jj] = &hall[(bgrp + 8 * jj) * HA_STR + kbeg];

#pragma unroll 4
        for (int kk = 0; kk < 256; kk += 4) {
            ulonglong2 wv[4], hv[4];
#pragma unroll
            for (int i = 0; i < 4; ++i)
                wv[i] = *reinterpret_cast<const ulonglong2*>(wsb[i] + kk);
#pragma unroll
            for (int jj = 0; jj < 4; ++jj)
                hv[jj] = *reinterpret_cast<const ulonglong2*>(hbb[jj] + kk);
#pragma unroll
            for (int i = 0; i < 4; ++i)
#pragma unroll
                for (int jj = 0; jj < 4; ++jj) {
                    ffma2(acc[i][jj], wv[i].x, hv[jj].x);
                    ffma2(acc[i][jj], wv[i].y, hv[jj].y);
                }
        }

        if (kh == 1) {
            float* rp = &red[r * RED_STR];
#pragma unroll
            for (int i = 0; i < 4; ++i)
#pragma unroll
                for (int jj = 0; jj < 4; ++jj)
                    rp[i * 4 + jj] = f2sum(acc[i][jj]);
        }
        __syncthreads();

        if (kh == 0) {
            float* hdst = g_hbuf[t & 1][dir];
            const float* rp = &red[r * RED_STR];
#pragma unroll
            for (int jj = 0; jj < 4; ++jj) {
                int b = b0 + bgrp + 8 * jj;
                float ig = f2sum(acc[0][jj]) + rp[0 * 4 + jj] + pf[0][jj];
                float fg = f2sum(acc[1][jj]) + rp[1 * 4 + jj] + pf[1][jj];
                float gg = f2sum(acc[2][jj]) + rp[2 * 4 + jj] + pf[2][jj];
                float og = f2sum(acc[3][jj]) + rp[3 * 4 + jj] + pf[3][jj];
                int L = Lb[jj];
                bool m = (t < L);
                float cn = sigf(fg) * creg[jj] + sigf(ig) * tanhf(gg);
                float hn = sigf(og) * tanhf(cn);
                if (m) { creg[jj] = cn; hreg[jj] = hn; }
                hdst[b * H_ + u] = hreg[jj];
                float outv = m ? hn : 0.0f;
                if (dir == 0) {
                    g_hf[((size_t)b * S_ + t) * H_ + u] = outv;
                } else {
                    int td = m ? (L - 1 - t) : t;
                    g_hb[((size_t)b * S_ + td) * H_ + u] = outv;
                }
            }
        }
        lstm_barrier(q, grp);
    }
}

// ---------------- K3: classifier logits = [hf,hb] @ Wc^T + bc ---------------
__global__ __launch_bounds__(256) void k_cls(const float* __restrict__ Wc,
                                             const float* __restrict__ bc,
                                             float* __restrict__ out) {
    __shared__ float hs[128 * 68];
    __shared__ float wcs[32 * 68];
    const int m0  = blockIdx.x * 128;
    const int tid = threadIdx.x;
    const int tq  = tid & 7;
    const int rq  = tid >> 3;
    const int tok0 = tq * 4, r0 = rq * 4;

    u64 acc[4][4];
#pragma unroll
    for (int i = 0; i < 4; ++i)
#pragma unroll
        for (int jm = 0; jm < 4; ++jm) acc[i][jm] = 0ull;

    for (int c = 0; c < 16; ++c) {
        __syncthreads();
        const float* src = (c < 8) ? g_hf : g_hb;
        const int kbase = (c & 7) * 64;
#pragma unroll
        for (int e = tid; e < 2048; e += 256) {
            int r = e >> 4, kq = e & 15;
            *reinterpret_cast<float4*>(&hs[r * 68 + kq * 4]) =
                *reinterpret_cast<const float4*>(&src[(size_t)(m0 + r) * 512 + kbase + kq * 4]);
        }
#pragma unroll
        for (int e = tid; e < 512; e += 256) {
            int tok = e >> 4, kq = e & 15;
            float4 v = make_float4(0.f, 0.f, 0.f, 0.f);
            if (tok < T_)
                v = *reinterpret_cast<const float4*>(&Wc[(size_t)tok * 1024 + c * 64 + kq * 4]);
            *reinterpret_cast<float4*>(&wcs[tok * 68 + kq * 4]) = v;
        }
        __syncthreads();
#pragma unroll
        for (int kk = 0; kk < 64; kk += 4) {
            ulonglong2 av[4], bv[4];
#pragma unroll
            for (int i = 0; i < 4; ++i)
                av[i] = *reinterpret_cast<const ulonglong2*>(&hs[(r0 + i) * 68 + kk]);
#pragma unroll
            for (int jm = 0; jm < 4; ++jm)
                bv[jm] = *reinterpret_cast<const ulonglong2*>(&wcs[(tok0 + jm) * 68 + kk]);
#pragma unroll
            for (int i = 0; i < 4; ++i)
#pragma unroll
                for (int jm = 0; jm < 4; ++jm) {
                    ffma2(acc[i][jm], av[i].x, bv[jm].x);
                    ffma2(acc[i][jm], av[i].y, bv[jm].y);
                }
        }
    }
#pragma unroll
    for (int jm = 0; jm < 4; ++jm) {
        int tok = tok0 + jm;
        if (tok < T_) {
            float bcv = bc[tok];
#pragma unroll
            for (int i = 0; i < 4; ++i)
                out[LOGITS_OFF + (size_t)(m0 + r0 + i) * T_ + tok] = f2sum(acc[i][jm]) + bcv;
        }
    }
}

// ---------------- K4: CRF forward (logsumexp), Viterbi, numerator -----------
__global__ __launch_bounds__(32) void k_crf(const float* __restrict__ out_logits,
                                            const int* __restrict__ labels,
                                            const float* __restrict__ trans,
                                            const float* __restrict__ start,
                                            const float* __restrict__ end,
                                            float* __restrict__ out) {
    __shared__ float trans_s[T_ * T_ + 8];
    __shared__ float sc[32], vv[32];
    __shared__ float end_s[T_], start_s[T_];
    __shared__ unsigned char hist[(S_ - 1) * T_];

    const int b = blockIdx.x;
    const int j = threadIdx.x;
    const int jc = (j < T_) ? j : (T_ - 1);
    const int L = g_len[b];
    const float* em = out_logits + LOGITS_OFF + (size_t)b * S_ * T_;
    const int* lab = labels + b * S_;

    for (int e = j; e < T_ * T_; e += 32) trans_s[e] = trans[e];
    if (j < T_) { end_s[j] = end[j]; start_s[j] = start[j]; }
    __syncwarp();

    float score  = (j < T_) ? (start_s[j] + em[j]) : -1e30f;
    float vscore = score;

    for (int t = 1; t < S_; ++t) {
        sc[j] = score; vv[j] = vscore;
        __syncwarp();
        bool m = (t < L);
        float e = (j < T_) ? em[t * T_ + j] : 0.0f;

        float mx = -1e30f;
        float bmax = -1e30f; int bi = 0;
#pragma unroll 5
        for (int i = 0; i < T_; ++i) {
            float tr = trans_s[i * T_ + jc];
            float v1 = sc[i] + tr;
            mx = fmaxf(mx, v1);
            float v2 = vv[i] + tr;
            if (v2 > bmax) { bmax = v2; bi = i; }
        }
        float smv = 0.0f;
#pragma unroll 5
        for (int i = 0; i < T_; ++i) {
            float v1 = sc[i] + trans_s[i * T_ + jc];
            smv += expf(v1 - mx);
        }
        if (j < T_) {
            hist[(t - 1) * T_ + j] = (unsigned char)(m ? bi : j);
            if (m) {
                score  = mx + logf(smv) + e;
                vscore = bmax + e;
            }
        }
        __syncwarp();
    }
    sc[j] = score; vv[j] = vscore;
    __syncwarp();

    float num = 0.0f;
    for (int t = 1 + j; t < S_; t += 32) {
        if (t < L) {
            int at  = lab[t];
            int at1 = lab[t - 1];
            num += trans_s[at1 * T_ + at] + em[t * T_ + at];
        }
    }
#pragma unroll
    for (int o = 16; o; o >>= 1) num += __shfl_xor_sync(0xffffffffu, num, o);

    if (j == 0) {
        int a0 = lab[0];
        num += start_s[a0] + em[a0] + end_s[lab[L - 1]];
        float mx = -1e30f;
        for (int i = 0; i < T_; ++i) mx = fmaxf(mx, sc[i] + end_s[i]);
        float smv = 0.0f;
        for (int i = 0; i < T_; ++i) smv += expf(sc[i] + end_s[i] - mx);
        float denom = mx + logf(smv);
        g_llh[b] = num - denom;

        float best = -1e30f; int tag = 0;
        for (int i = 0; i < T_; ++i) {
            float v = vv[i] + end_s[i];
            if (v > best) { best = v; tag = i; }
        }
        out[TAGS_OFF + b * S_ + (S_ - 1)] = (float)tag;
        for (int t = S_ - 2; t >= 0; --t) {
            if ((t + 1) < L) tag = hist[t * T_ + tag];
            out[TAGS_OFF + b * S_ + t] = (float)tag;
        }
    }
}

// ---------------- K5: loss reduction ----------------------------------------
__global__ void k_loss(float* __restrict__ out) {
    __shared__ float sv[64];
    __shared__ int scn[64];
    int tid = threadIdx.x;
    sv[tid]  = g_llh[tid];
    scn[tid] = g_len[tid];
    __syncthreads();
    if (tid == 0) {
        float s = 0.0f; int n = 0;
        for (int i = 0; i < 64; ++i) { s += sv[i]; n += scn[i]; }
        out[0] = -(s / (float)n);
    }
}

// ---------------- launch -----------------------------------------------------
extern "C" void kernel_launch(void* const* d_in, const int* in_sizes, int n_in,
                              void* d_out, int out_size) {
    const float* x       = (const float*)d_in[0];
    const float* W_ih_f  = (const float*)d_in[1];
    const float* W_hh_f  = (const float*)d_in[2];
    const float* b_f     = (const float*)d_in[3];
    const float* W_ih_b  = (const float*)d_in[4];
    const float* W_hh_b  = (const float*)d_in[5];
    const float* b_b     = (const float*)d_in[6];
    const float* Wc      = (const float*)d_in[7];
    const float* bc      = (const float*)d_in[8];
    const float* c_start = (const float*)d_in[9];
    const float* c_end   = (const float*)d_in[10];
    const float* c_trans = (const float*)d_in[11];
    const int*   amask   = (const int*)d_in[12];
    const int*   labels  = (const int*)d_in[13];
    float* out = (float*)d_out;

    const size_t smem_lstm = (64 * WS_STR + 32 * HA_STR + 128 * RED_STR) * sizeof(float);
    cudaFuncSetAttribute(k_lstm, cudaFuncAttributeMaxDynamicSharedMemorySize, (int)smem_lstm);
    cudaFuncSetAttribute(k_pre,  cudaFuncAttributeMaxDynamicSharedMemorySize, SM_PRE_BYTES);

    k_len<<<B_, 256>>>(amask, out);
    k_cvt<<<((NROW_ + 4096) * 40 + 255) / 256, 256>>>(x, W_ih_f, W_ih_b);
    k_pre<<<dim3(NROW_ / BM, 4096 / BN), 256, SM_PRE_BYTES>>>(b_f, b_b);
    k_lstm<<<128, 256, smem_lstm>>>(W_hh_f, W_hh_b);
    k_cls<<<256, 256>>>(Wc, bc, out);
    k_crf<<<B_, 32>>>(out, labels, c_trans, c_start, c_end, out);
    k_loss<<<1, 64>>>(out);
}